// round 13
// baseline (speedup 1.0000x reference)
#include <cuda_runtime.h>
#include <math.h>

// Problem constants: B=4, L=512, E=1024, H=128
#define LL 512
#define EE 1024
#define HH 128
#define NB 4

// Scratch (device globals: no allocation allowed)
__device__ float g_hpart[2 * 4096 * HH];  // split-K partial sums (pre-bias/ReLU)
__device__ float g_part[256];             // per (batch, tile) partial max
__device__ unsigned int g_ctr;            // bilinear CTA-done counter

__device__ __forceinline__ float fast_tanh(float x) {
    float y;
    asm("tanh.approx.f32 %0, %1;" : "=f"(y) : "f"(x));
    return y;
}

__device__ __forceinline__ void fma_f32x2(unsigned long long& c,
                                          unsigned long long a,
                                          unsigned long long b) {
    asm("fma.rn.f32x2 %0, %1, %2, %0;" : "+l"(c) : "l"(a), "l"(b));
}

__device__ __forceinline__ float2 unpack_f32x2(unsigned long long v) {
    float2 r;
    asm("mov.b64 {%0, %1}, %2;" : "=f"(r.x), "=f"(r.y) : "l"(v));
    return r;
}

// ---------------------------------------------------------------------------
// Kernel 1: split-K GEMM partials via packed FFMA2.
// part[kz] = X @ W1[kz*512:(kz+1)*512]   (M=4096, N=128)
// BM=64, BN=64, BK=16, 256 threads, 4x4 micro-tile, double-buffered.
// A stored DUPLICATED in smem: As2[k][2m]=As2[k][2m+1]=a  ->  ld.shared.b64
// yields (a,a) pairs directly; B pairs (b0,b1) are native b64 loads.
// Inner k-step: 3x LDS.128 + 8x fma.rn.f32x2  (vs 2 LDS + 16 FFMA before).
// ---------------------------------------------------------------------------
#define AD 128   // duplicated A row width (64 rows x 2)

__global__ __launch_bounds__(256) void gemm_hid_kernel(
    const float* __restrict__ rec, const float* __restrict__ lig,
    const float* __restrict__ W1)
{
    __shared__ __align__(16) float As2[2][16][AD];
    __shared__ __align__(16) float Bs[2][16][64];
    const int bx = blockIdx.x;   // h tile: 0..1
    const int by = blockIdx.y;   // m tile: 0..63
    const int bz = blockIdx.z;   // k half: 0..1
    const int tid = threadIdx.x;
    const int tx = tid & 15, ty = tid >> 4;

    // fill-role indices
    const int a_row = tid >> 2;          // 0..63
    const int a_e0  = (tid & 3) * 4;     // 0,4,8,12
    const int b_row = tid >> 4;          // 0..15
    const int b_h0  = (tid & 15) * 4;    // 0..60

    const int m_global = by * 64 + a_row;
    const float* src = ((m_global < 2048)
        ? rec + (size_t)m_global * EE
        : lig + (size_t)(m_global - 2048) * EE) + bz * 512;
    const float* wsrc = W1 + (size_t)(bz * 512 + b_row) * HH + bx * 64 + b_h0;

    unsigned long long c2[4][2] = {};    // (j0,j1),(j2,j3) packed per row i

    // prefetch tile 0
    float4 av = *(const float4*)(src + a_e0);
    float4 bv = *(const float4*)(wsrc);

    int buf = 0;
    for (int kk = 0; kk < 32; kk++) {
        // commit prefetched tile (A duplicated)
        *(float2*)&As2[buf][a_e0 + 0][2 * a_row] = make_float2(av.x, av.x);
        *(float2*)&As2[buf][a_e0 + 1][2 * a_row] = make_float2(av.y, av.y);
        *(float2*)&As2[buf][a_e0 + 2][2 * a_row] = make_float2(av.z, av.z);
        *(float2*)&As2[buf][a_e0 + 3][2 * a_row] = make_float2(av.w, av.w);
        *(float4*)&Bs[buf][b_row][b_h0] = bv;
        __syncthreads();

        if (kk < 31) {
            av = *(const float4*)(src + (kk + 1) * 16 + a_e0);
            bv = *(const float4*)(wsrc + (size_t)(kk + 1) * 16 * HH);
        }

        #pragma unroll
        for (int k = 0; k < 16; k++) {
            const unsigned long long* ap =
                (const unsigned long long*)&As2[buf][k][8 * ty];
            const unsigned long long* bp =
                (const unsigned long long*)&Bs[buf][k][tx * 4];
            unsigned long long a0 = ap[0], a1 = ap[1], a2 = ap[2], a3 = ap[3];
            unsigned long long b01 = bp[0], b23 = bp[1];
            fma_f32x2(c2[0][0], a0, b01); fma_f32x2(c2[0][1], a0, b23);
            fma_f32x2(c2[1][0], a1, b01); fma_f32x2(c2[1][1], a1, b23);
            fma_f32x2(c2[2][0], a2, b01); fma_f32x2(c2[2][1], a2, b23);
            fma_f32x2(c2[3][0], a3, b01); fma_f32x2(c2[3][1], a3, b23);
        }
        buf ^= 1;
        // WAR hazard on the other buffer is two iterations away, separated
        // by the next iteration's __syncthreads -> safe.
    }

    float* dst = g_hpart + (size_t)bz * 4096 * HH;
    #pragma unroll
    for (int i = 0; i < 4; i++) {
        int m = by * 64 + ty * 4 + i;
        float2 lo = unpack_f32x2(c2[i][0]);
        float2 hi = unpack_f32x2(c2[i][1]);
        float4 o = {lo.x, lo.y, hi.x, hi.y};
        *(float4*)&dst[(size_t)m * HH + bx * 64 + tx * 4] = o;
    }
}

// ---------------------------------------------------------------------------
// Kernel 2: fused (split-K combine + bias + ReLU) + tanh-outer-product
//           + conv2x2 + max, with last-CTA finalize (no separate kernels).
// CTA tile: 32 (i) x 128 (j). 256 threads, grid (4,16,4)=256 CTAs.
//   ty = warp id: rows 4ty..4ty+3 -> r rows WARP-UNIFORM; ReLU zero-row
//        skip wrapped in __any_sync so ptxas sees a uniform branch.
//   tx = tid&31: cols 4tx..4tx+3; float4 LDS at 16B/lane -> conflict-free.
// Per-thread 4x4 outputs via 5x5 tanh halo. H chunked 4 x 32.
// ---------------------------------------------------------------------------
#define RST 36     // 33 halo rows padded
#define LST 132    // 129 halo cols padded (132*4 % 16 == 0)

__global__ __launch_bounds__(256) void bilinear_max_kernel(
    const float* __restrict__ convw, const float* __restrict__ b1,
    const float* __restrict__ convb, float* __restrict__ out)
{
    __shared__ __align__(16) float rs[32 * RST];   // [h][halo row]
    __shared__ __align__(16) float ls[32 * LST];   // [h][halo col]
    __shared__ __align__(16) float ws4[512];       // conv weights [h][2][2]
    __shared__ float bsh[HH];                      // bias
    __shared__ float red[256];
    __shared__ int lastflag;

    const int b  = blockIdx.z;
    const int it = blockIdx.y;     // 0..15
    const int jt = blockIdx.x;     // 0..3
    const int tid = threadIdx.x;
    const int tx = tid & 31;
    const int ty = tid >> 5;       // warp id (warp-uniform rows)
    const int i0 = it * 32, j0 = jt * 128;

    const float* p0 = g_hpart;
    const float* p1 = g_hpart + 4096 * HH;

    for (int idx = tid; idx < 512; idx += 256) ws4[idx] = convw[idx];
    for (int idx = tid; idx < HH; idx += 256) bsh[idx] = b1[idx];

    float acc[4][4] = {};

    for (int hc = 0; hc < 4; hc++) {
        __syncthreads();   // previous chunk consumed (and ws4/bsh on hc=0)
        // fill halo tiles; fuse split-K combine + bias + ReLU here
        for (int idx = tid; idx < 33 * 32; idx += 256) {
            int row = idx >> 5, hh = idx & 31;
            int gi = i0 - 1 + row;
            float v = 0.f;
            if (gi >= 0) {
                size_t off = (size_t)(b * LL + gi) * HH + hc * 32 + hh;
                v = fmaxf(p0[off] + p1[off] + bsh[hc * 32 + hh], 0.f);
            }
            rs[hh * RST + row] = v;
        }
        for (int idx = tid; idx < 129 * 32; idx += 256) {
            int col = idx >> 5, hh = idx & 31;
            int gj = j0 - 1 + col;
            float v = 0.f;
            if (gj >= 0) {
                size_t off = (size_t)(2048 + b * LL + gj) * HH + hc * 32 + hh;
                v = fmaxf(p0[off] + p1[off] + bsh[hc * 32 + hh], 0.f);
            }
            ls[hh * LST + col] = v;
        }
        __syncthreads();

        #pragma unroll 1
        for (int hh = 0; hh < 32; hh++) {
            const float* rp = rs + hh * RST + 4 * ty;   // halo rows (uniform)
            const float* lp = ls + hh * LST + 4 * tx;
            float rr[5];
            #pragma unroll
            for (int r = 0; r < 5; r++) rr[r] = rp[r];  // warp-uniform bcast
            float4 a4 = *(const float4*)lp;  float a5 = lp[4];
            float la[5] = {a4.x, a4.y, a4.z, a4.w, a5};
            float4 w4 = *(const float4*)(ws4 + (hc * 32 + hh) * 4);

            #pragma unroll
            for (int u = 0; u < 5; u++) {
                float rv = rr[u];
                // rv is warp-uniform; __any_sync makes that provable
                if (__any_sync(0xFFFFFFFFu, rv != 0.f)) {
                    float t[5];
                    #pragma unroll
                    for (int v = 0; v < 5; v++) t[v] = fast_tanh(rv * la[v]);
                    if (u < 4) {            // t row u as dp=0 for output row u
                        #pragma unroll
                        for (int q = 0; q < 4; q++)
                            acc[u][q] += w4.x * t[q] + w4.y * t[q + 1];
                    }
                    if (u > 0) {            // t row u as dp=1 for row u-1
                        #pragma unroll
                        for (int q = 0; q < 4; q++)
                            acc[u - 1][q] += w4.z * t[q] + w4.w * t[q + 1];
                    }
                }
            }
        }
    }

    float m = acc[0][0];
    #pragma unroll
    for (int a = 0; a < 4; a++)
        #pragma unroll
        for (int q = 0; q < 4; q++)
            m = fmaxf(m, acc[a][q]);

    red[tid] = m;
    __syncthreads();
    #pragma unroll
    for (int s = 128; s > 0; s >>= 1) {
        if (tid < s) red[tid] = fmaxf(red[tid], red[tid + s]);
        __syncthreads();
    }

    // publish tile max; last CTA to finish does the finalize inline
    if (tid == 0) {
        g_part[b * 64 + it * 4 + jt] = red[0];
        __threadfence();
        unsigned t = atomicAdd(&g_ctr, 1u);
        lastflag = (t == 255u);
    }
    __syncthreads();
    if (lastflag) {
        __threadfence();   // acquire: make all CTAs' g_part writes visible
        if (tid < 128) {
            int w = tid >> 5, lane = tid & 31;
            float mm = fmaxf(g_part[w * 64 + lane], g_part[w * 64 + 32 + lane]);
            #pragma unroll
            for (int s = 16; s > 0; s >>= 1)
                mm = fmaxf(mm, __shfl_xor_sync(0xFFFFFFFFu, mm, s));
            if (lane == 0) {
                float y = mm + convb[0];
                out[w] = 1.f / (1.f + expf(-y));
            }
        }
        if (tid == 0) g_ctr = 0;   // reset for next graph replay
    }
}

extern "C" void kernel_launch(void* const* d_in, const int* in_sizes, int n_in,
                              void* d_out, int out_size)
{
    const float* rec   = (const float*)d_in[0];
    const float* lig   = (const float*)d_in[1];
    const float* W1    = (const float*)d_in[2];
    const float* b1    = (const float*)d_in[3];
    const float* convw = (const float*)d_in[4];
    const float* convb = (const float*)d_in[5];
    float* out = (float*)d_out;

    gemm_hid_kernel<<<dim3(2, 64, 2), 256>>>(rec, lig, W1);
    bilinear_max_kernel<<<dim3(4, 16, 4), 256>>>(convw, b1, convb, out);
}